// round 6
// baseline (speedup 1.0000x reference)
#include <cuda_runtime.h>
#include <math.h>

#define WPB 8
#define PW 4692                     // floats/warp: Xs 1156 + Qs 1156 + Ks 1156 + S 1224
#define TABF 1904                   // dmask 4*17*20 + sin 272 + cos 272
#define SMEMF (WPB*PW + TABF)

typedef unsigned long long u64;

__device__ __forceinline__ u64 pk2(float lo, float hi) {
    u64 r; asm("mov.b64 %0, {%1, %2};" : "=l"(r) : "f"(lo), "f"(hi)); return r;
}
__device__ __forceinline__ void fma2(u64& d, u64 a, u64 b) {
    asm("fma.rn.f32x2 %0, %1, %2, %0;" : "+l"(d) : "l"(a), "l"(b));
}
__device__ __forceinline__ float hadd2(u64 a) {
    float lo, hi; asm("mov.b64 {%0, %1}, %2;" : "=f"(lo), "=f"(hi) : "l"(a));
    return lo + hi;
}

__device__ __forceinline__ float wsum(float v) {
#pragma unroll
    for (int d = 16; d > 0; d >>= 1) v += __shfl_xor_sync(0xffffffffu, v, d);
    return v;
}

__global__ void __launch_bounds__(256, 1) vit_kernel(
    const float* __restrict__ x,      const float* __restrict__ patch_w,
    const float* __restrict__ patch_b,const float* __restrict__ cls,
    const float* __restrict__ pos,
    const float* __restrict__ Wq, const float* __restrict__ Wk,
    const float* __restrict__ Wv, const float* __restrict__ Wg,
    const float* __restrict__ Wo,
    const float* __restrict__ ln1_s, const float* __restrict__ ln1_b,
    const float* __restrict__ w1, const float* __restrict__ b1,
    const float* __restrict__ w2, const float* __restrict__ b2,
    const float* __restrict__ ln2_s, const float* __restrict__ ln2_b,
    const float* __restrict__ lnf_s, const float* __restrict__ lnf_b,
    const float* __restrict__ neck_w, const float* __restrict__ neck_b,
    const float* __restrict__ head_w, const float* __restrict__ head_b,
    float* __restrict__ out, int nimg)
{
    extern __shared__ float sm[];
    const int tid = threadIdx.x;
    const int warp = tid >> 5, lane = tid & 31;

    float* wb = sm + warp * PW;
    float* Xs = wb;                 // [17][68]   (also patch staging [16][192])
    float* Qs = wb + 1156;          // [17][68]   (reused: Gs[17][132], Gf, neck)
    float* Ks = wb + 2312;          // [17][68]
    float* Ssc= wb + 3468;          // [68][18]   normalized scores (dmask+den folded)
    float* tab = sm + WPB * PW;
    float* DM = tab;                // [4][17][20]
    float* SN = tab + 1360;         // [17][16]
    float* CS = tab + 1632;         // [17][16]

    // ---- per-CTA tables ----
    if (tid < 68) {
        int hh = tid / 17, n = tid % 17;
        float l0 = logf(1.0f / 32.0f), l1 = logf(1.0f / 512.0f);
        float gam = 1.0f - expf(l0 + (l1 - l0) * ((float)hh / 3.0f));
        float lg = logf(gam);
        float row[17]; float s = 0.f;
#pragma unroll
        for (int m = 0; m < 17; m++) {
            float v = (m <= n) ? expf(lg * (float)(n - m)) : 0.f;
            row[m] = v; s += v;
        }
        float nf = rsqrtf(s) * 0.25f;    // 0.25 = QH^-0.5 folded in
#pragma unroll
        for (int m = 0; m < 17; m++) DM[(hh * 17 + n) * 20 + m] = row[m] * nf;
    }
    for (int i = tid; i < 272; i += 256) {
        int t = i >> 4, j = i & 15;
        float e = (float)(j >> 1) / 7.0f;
        float ang = expf(-e * logf(10000.0f));
        float a = (float)t * ang;
        SN[i] = sinf(a); CS[i] = cosf(a);
    }
    __syncthreads();

    const int col = lane * 2;    // lane's 2 cols of D=64 tensors
    const int c4  = lane * 4;    // lane's 4 cols of V=128 tensors
    const int hh4 = lane >> 3;   // head owning cols c4..c4+3

    for (int img = blockIdx.x * WPB + warp; img < nimg; img += gridDim.x * WPB) {
        // ================= patch embed =================
        const float* xi = x + (long)img * 3072;
        for (int i = lane; i < 3072; i += 32) {
            int c = i >> 10, rem = i & 1023, yy = rem >> 5, xx = rem & 31;
            int p = ((yy >> 3) << 2) + (xx >> 3);
            int f = (c << 6) + ((yy & 7) << 3) + (xx & 7);
            wb[p * 192 + f] = xi[i];          // staging [16][192] (f-contiguous)
        }
        __syncwarp();
        float2 h2[17];
        {
            u64 ax[16], ay[16];
#pragma unroll
            for (int p = 0; p < 16; p++) { ax[p] = 0ull; ay[p] = 0ull; }
#pragma unroll 2
            for (int fp = 0; fp < 96; fp++) {
                int f = fp * 2;
                float2 wa = *(const float2*)(patch_w + f * 64 + col);
                float2 wbv= *(const float2*)(patch_w + (f + 1) * 64 + col);
                u64 wx2 = pk2(wa.x, wbv.x), wy2 = pk2(wa.y, wbv.y);
#pragma unroll
                for (int p = 0; p < 16; p++) {
                    u64 xp = *(const u64*)(wb + p * 192 + f);
                    fma2(ax[p], xp, wx2); fma2(ay[p], xp, wy2);
                }
            }
            __syncwarp();
            float2 pb = *(const float2*)(patch_b + col);
            float2 cl = *(const float2*)(cls + col);
            float2 p0 = *(const float2*)(pos + col);
            h2[0] = make_float2(cl.x + p0.x, cl.y + p0.y);
#pragma unroll
            for (int t = 1; t < 17; t++) {
                float2 po = *(const float2*)(pos + t * 64 + col);
                h2[t] = make_float2(hadd2(ax[t-1]) + pb.x + po.x,
                                    hadd2(ay[t-1]) + pb.y + po.y);
            }
        }

        // ================= transformer layers =================
#pragma unroll 1
        for (int L = 0; L < 8; L++) {
            const float* wq = Wq + L * 4096;
            const float* wk = Wk + L * 4096;
            const float* wv = Wv + L * 8192;
            const float* wg = Wg + L * 8192;
            const float* wo = Wo + L * 8192;

            // ---- LN1 -> Xs ----
            {
                float2 ls = *(const float2*)(ln1_s + L * 64 + col);
                float2 lb = *(const float2*)(ln1_b + L * 64 + col);
#pragma unroll
                for (int t = 0; t < 17; t++) {
                    float s = wsum(h2[t].x + h2[t].y);
                    float q = wsum(h2[t].x * h2[t].x + h2[t].y * h2[t].y);
                    float mu = s * (1.0f / 64.0f);
                    float var = q * (1.0f / 64.0f) - mu * mu;
                    float r = rsqrtf(var + 1e-5f);
                    *(float2*)(Xs + t * 68 + col) =
                        make_float2((h2[t].x - mu) * r * ls.x + lb.x,
                                    (h2[t].y - mu) * r * ls.y + lb.y);
                }
            }
            __syncwarp();

            // ---- q,k = Xs @ Wq/Wk (f32x2 reduction-packed, 2 token passes), rope ----
            {
                int cc = col & 15;
#pragma unroll
                for (int half = 0; half < 2; half++) {
                    int t0 = half * 9;
                    u64 aqx[9], aqy[9], akx[9], aky[9];
#pragma unroll
                    for (int j = 0; j < 9; j++) { aqx[j]=0ull; aqy[j]=0ull; akx[j]=0ull; aky[j]=0ull; }
#pragma unroll 2
                    for (int kp = 0; kp < 32; kp++) {
                        int k = kp * 2;
                        float2 qa_ = *(const float2*)(wq + k * 64 + col);
                        float2 qb_ = *(const float2*)(wq + (k + 1) * 64 + col);
                        float2 ka_ = *(const float2*)(wk + k * 64 + col);
                        float2 kb_ = *(const float2*)(wk + (k + 1) * 64 + col);
                        u64 qx2 = pk2(qa_.x, qb_.x), qy2 = pk2(qa_.y, qb_.y);
                        u64 kx2 = pk2(ka_.x, kb_.x), ky2 = pk2(ka_.y, kb_.y);
#pragma unroll
                        for (int j = 0; j < 9; j++) {
                            if (t0 + j < 17) {
                                u64 xp = *(const u64*)(Xs + (t0 + j) * 68 + k);
                                fma2(aqx[j], xp, qx2); fma2(aqy[j], xp, qy2);
                                fma2(akx[j], xp, kx2); fma2(aky[j], xp, ky2);
                            }
                        }
                    }
#pragma unroll
                    for (int j = 0; j < 9; j++) {
                        int t = t0 + j;
                        if (t < 17) {
                            float qx = hadd2(aqx[j]), qy = hadd2(aqy[j]);
                            float kx = hadd2(akx[j]), ky = hadd2(aky[j]);
                            float sn = SN[t * 16 + cc], cn = CS[t * 16 + cc];
                            *(float2*)(Qs + t*68 + col) =
                                make_float2(qx*cn - qy*sn, qy*cn + qx*sn);
                            *(float2*)(Ks + t*68 + col) =
                                make_float2(kx*cn - ky*sn, ky*cn + kx*sn);
                        }
                    }
                }
            }

            // ---- v = Xs @ Wv (f32x2, 2 passes) -> va scalars ----
            float4 va[17];
            {
#pragma unroll
                for (int half = 0; half < 2; half++) {
                    int t0 = half * 9;
                    u64 ax[9], ay[9], az[9], aw[9];
#pragma unroll
                    for (int j = 0; j < 9; j++) { ax[j]=0ull; ay[j]=0ull; az[j]=0ull; aw[j]=0ull; }
#pragma unroll 2
                    for (int kp = 0; kp < 32; kp++) {
                        int k = kp * 2;
                        float4 a_ = *(const float4*)(wv + k * 128 + c4);
                        float4 b_ = *(const float4*)(wv + (k + 1) * 128 + c4);
                        u64 px = pk2(a_.x, b_.x), py = pk2(a_.y, b_.y);
                        u64 pz = pk2(a_.z, b_.z), pw = pk2(a_.w, b_.w);
#pragma unroll
                        for (int j = 0; j < 9; j++) {
                            if (t0 + j < 17) {
                                u64 xp = *(const u64*)(Xs + (t0 + j) * 68 + k);
                                fma2(ax[j], xp, px); fma2(ay[j], xp, py);
                                fma2(az[j], xp, pz); fma2(aw[j], xp, pw);
                            }
                        }
                    }
#pragma unroll
                    for (int j = 0; j < 9; j++) {
                        int t = t0 + j;
                        if (t < 17)
                            va[t] = make_float4(hadd2(ax[j]), hadd2(ay[j]),
                                                hadd2(az[j]), hadd2(aw[j]));
                    }
                }
            }
            __syncwarp();

            // ---- stage A: normalized scores -> Ssc[68][18] (zero beyond n) ----
#pragma unroll 1
            for (int r = lane; r < 68; r += 32) {
                int hh = r & 3, n = r >> 2;
                const float* qp = Qs + n * 68 + hh * 16;
                float4 q0 = *(const float4*)(qp);
                float4 q1 = *(const float4*)(qp + 4);
                float4 q2 = *(const float4*)(qp + 8);
                float4 q3 = *(const float4*)(qp + 12);
                const float* dmr = DM + (hh * 17 + n) * 20;
                float sv[17]; float ssum = 0.f;
#pragma unroll
                for (int m = 0; m < 17; m++) {
                    if (m <= n) {
                        const float* kp = Ks + m * 68 + hh * 16;
                        float4 k0 = *(const float4*)(kp);
                        float4 k1 = *(const float4*)(kp + 4);
                        float4 k2 = *(const float4*)(kp + 8);
                        float4 k3 = *(const float4*)(kp + 12);
                        float s = q0.x*k0.x + q0.y*k0.y + q0.z*k0.z + q0.w*k0.w
                                + q1.x*k1.x + q1.y*k1.y + q1.z*k1.z + q1.w*k1.w
                                + q2.x*k2.x + q2.y*k2.y + q2.z*k2.z + q2.w*k2.w
                                + q3.x*k3.x + q3.y*k3.y + q3.z*k3.z + q3.w*k3.w;
                        s *= dmr[m];
                        sv[m] = s; ssum += s;
                    }
                }
                float den = fabsf(ssum); den = den > 1.f ? den : 1.f;
                float inv = 1.f / den;
                float* sp = Ssc + (hh * 17 + n) * 18;
#pragma unroll
                for (int m = 0; m < 17; m++) sp[m] = (m <= n) ? sv[m] * inv : 0.f;
                sp[17] = 0.f;
            }
            __syncwarp();

            // ---- stage B: o = S @ v (f32x2, packed along m, causal) + groupnorm ----
            float4 ov[17];
            {
                u64 vx2[9], vy2[9], vz2[9], vw2[9];
#pragma unroll
                for (int mp = 0; mp < 9; mp++) {
                    float4 a = va[2 * mp];
                    float4 b = (2 * mp + 1 < 17) ? va[2 * mp + 1] : make_float4(0,0,0,0);
                    vx2[mp] = pk2(a.x, b.x); vy2[mp] = pk2(a.y, b.y);
                    vz2[mp] = pk2(a.z, b.z); vw2[mp] = pk2(a.w, b.w);
                }
                const float* Sb = Ssc + hh4 * 17 * 18;
#pragma unroll
                for (int n = 0; n < 17; n++) {
                    u64 a0 = 0ull, a1 = 0ull, a2 = 0ull, a3 = 0ull;
                    const float* sp = Sb + n * 18;
#pragma unroll
                    for (int mp = 0; mp <= (n >> 1); mp++) {
                        u64 s2 = *(const u64*)(sp + 2 * mp);
                        fma2(a0, s2, vx2[mp]); fma2(a1, s2, vy2[mp]);
                        fma2(a2, s2, vz2[mp]); fma2(a3, s2, vw2[mp]);
                    }
                    float4 o = make_float4(hadd2(a0), hadd2(a1), hadd2(a2), hadd2(a3));
                    float pm = o.x + o.y + o.z + o.w;
                    float pq = o.x*o.x + o.y*o.y + o.z*o.z + o.w*o.w;
#pragma unroll
                    for (int d = 1; d < 8; d <<= 1) {
                        pm += __shfl_xor_sync(0xffffffffu, pm, d);
                        pq += __shfl_xor_sync(0xffffffffu, pq, d);
                    }
                    float mu = pm * (1.0f / 32.0f);
                    float var = pq * (1.0f / 32.0f) - mu * mu;
                    float rn = rsqrtf(var + 1e-5f);
                    ov[n] = make_float4((o.x - mu) * rn, (o.y - mu) * rn,
                                        (o.z - mu) * rn, (o.w - mu) * rn);
                }
            }

            // ---- g = Xs @ Wg (f32x2, 2 passes); Gs = silu(g) * ov ----
            {
                float* Gs = Qs;
#pragma unroll
                for (int half = 0; half < 2; half++) {
                    int t0 = half * 9;
                    u64 ax[9], ay[9], az[9], aw[9];
#pragma unroll
                    for (int j = 0; j < 9; j++) { ax[j]=0ull; ay[j]=0ull; az[j]=0ull; aw[j]=0ull; }
#pragma unroll 2
                    for (int kp = 0; kp < 32; kp++) {
                        int k = kp * 2;
                        float4 a_ = *(const float4*)(wg + k * 128 + c4);
                        float4 b_ = *(const float4*)(wg + (k + 1) * 128 + c4);
                        u64 px = pk2(a_.x, b_.x), py = pk2(a_.y, b_.y);
                        u64 pz = pk2(a_.z, b_.z), pw = pk2(a_.w, b_.w);
#pragma unroll
                        for (int j = 0; j < 9; j++) {
                            if (t0 + j < 17) {
                                u64 xp = *(const u64*)(Xs + (t0 + j) * 68 + k);
                                fma2(ax[j], xp, px); fma2(ay[j], xp, py);
                                fma2(az[j], xp, pz); fma2(aw[j], xp, pw);
                            }
                        }
                    }
#pragma unroll
                    for (int j = 0; j < 9; j++) {
                        int t = t0 + j;
                        if (t < 17) {
                            float4 g = make_float4(hadd2(ax[j]), hadd2(ay[j]),
                                                   hadd2(az[j]), hadd2(aw[j]));
                            float4 o = ov[t];
                            float4 rr;
                            rr.x = g.x / (1.f + expf(-g.x)) * o.x;
                            rr.y = g.y / (1.f + expf(-g.y)) * o.y;
                            rr.z = g.z / (1.f + expf(-g.z)) * o.z;
                            rr.w = g.w / (1.f + expf(-g.w)) * o.w;
                            *(float4*)(Gs + t * 132 + c4) = rr;
                        }
                    }
                }
            }
            __syncwarp();

            // ---- attn out = Gs @ Wo (f32x2 reduction-packed), residual ----
            {
                const float* Gs = Qs;
                u64 aox[17], aoy[17];
#pragma unroll
                for (int t = 0; t < 17; t++) { aox[t] = 0ull; aoy[t] = 0ull; }
#pragma unroll 2
                for (int kp = 0; kp < 64; kp++) {
                    int k = kp * 2;
                    float2 wa = *(const float2*)(wo + k * 64 + col);
                    float2 wbv= *(const float2*)(wo + (k + 1) * 64 + col);
                    u64 wx2 = pk2(wa.x, wbv.x), wy2 = pk2(wa.y, wbv.y);
#pragma unroll
                    for (int t = 0; t < 17; t++) {
                        u64 gp = *(const u64*)(Gs + t * 132 + k);
                        fma2(aox[t], gp, wx2); fma2(aoy[t], gp, wy2);
                    }
                }
#pragma unroll
                for (int t = 0; t < 17; t++) {
                    h2[t].x += hadd2(aox[t]); h2[t].y += hadd2(aoy[t]);
                }
            }

            // ---- LN2 -> Xs ----
            {
                float2 ls = *(const float2*)(ln2_s + L * 64 + col);
                float2 lb = *(const float2*)(ln2_b + L * 64 + col);
#pragma unroll
                for (int t = 0; t < 17; t++) {
                    float s = wsum(h2[t].x + h2[t].y);
                    float q = wsum(h2[t].x * h2[t].x + h2[t].y * h2[t].y);
                    float mu = s * (1.0f / 64.0f);
                    float var = q * (1.0f / 64.0f) - mu * mu;
                    float r = rsqrtf(var + 1e-5f);
                    *(float2*)(Xs + t * 68 + col) =
                        make_float2((h2[t].x - mu) * r * ls.x + lb.x,
                                    (h2[t].y - mu) * r * ls.y + lb.y);
                }
            }
            __syncwarp();

            // ---- FFN: gelu(Xs @ w1 + b1) -> Gf ----
            {
                float* Gf = Qs;
                const float* pw1 = w1 + L * 768;
                const float* pb1 = b1 + L * 12;
#pragma unroll 1
                for (int r = lane; r < 204; r += 32) {
                    int t = r / 12, j = r - t * 12;
                    float s = pb1[j];
                    const float* xr = Xs + t * 68;
#pragma unroll
                    for (int k4 = 0; k4 < 64; k4 += 4) {
                        float4 xv = *(const float4*)(xr + k4);
                        s += xv.x * pw1[(k4+0)*12 + j] + xv.y * pw1[(k4+1)*12 + j]
                           + xv.z * pw1[(k4+2)*12 + j] + xv.w * pw1[(k4+3)*12 + j];
                    }
                    float c = 0.7978845608028654f * (s + 0.044715f * s * s * s);
                    Gf[r] = 0.5f * s * (1.f + tanhf(c));
                }
            }
            __syncwarp();

            // ---- h += Gf @ w2 + b2 (f32x2 reduction-packed) ----
            {
                const float* Gf = Qs;
                const float* pw2 = w2 + L * 768;
                float2 b2v = *(const float2*)(b2 + L * 64 + col);
                u64 w2x[6], w2y[6];
#pragma unroll
                for (int kp = 0; kp < 6; kp++) {
                    float2 a = *(const float2*)(pw2 + (2*kp) * 64 + col);
                    float2 b = *(const float2*)(pw2 + (2*kp+1) * 64 + col);
                    w2x[kp] = pk2(a.x, b.x); w2y[kp] = pk2(a.y, b.y);
                }
#pragma unroll
                for (int t = 0; t < 17; t++) {
                    u64 ax = 0ull, ay = 0ull;
#pragma unroll
                    for (int kp = 0; kp < 6; kp++) {
                        u64 g2 = *(const u64*)(Gf + t * 12 + 2 * kp);
                        fma2(ax, g2, w2x[kp]); fma2(ay, g2, w2y[kp]);
                    }
                    h2[t].x += hadd2(ax) + b2v.x;
                    h2[t].y += hadd2(ay) + b2v.y;
                }
            }
            __syncwarp();
        } // layers

        // ================= final LN (token 16) + neck + head =================
        {
            float2 hv = h2[16];
            float s = wsum(hv.x + hv.y);
            float q = wsum(hv.x * hv.x + hv.y * hv.y);
            float mu = s * (1.0f / 64.0f);
            float var = q * (1.0f / 64.0f) - mu * mu;
            float r = rsqrtf(var + 1e-5f);
            float2 ls = *(const float2*)(lnf_s + col);
            float2 lb = *(const float2*)(lnf_b + col);
            Xs[col]   = (hv.x - mu) * r * ls.x + lb.x;
            Xs[col+1] = (hv.y - mu) * r * ls.y + lb.y;
        }
        __syncwarp();
        if (lane < 16) {
            float s = neck_b[lane];
#pragma unroll
            for (int k = 0; k < 64; k++) s += Xs[k] * neck_w[k * 16 + lane];
            Qs[lane] = s;
        }
        __syncwarp();
        if (lane < 10) {
            float s = head_b[lane];
#pragma unroll
            for (int k = 0; k < 16; k++) s += Qs[k] * head_w[k * 10 + lane];
            out[(long)img * 10 + lane] = s;
        }
        __syncwarp();
    } // img loop
}

extern "C" void kernel_launch(void* const* d_in, const int* in_sizes, int n_in,
                              void* d_out, int out_size) {
    const float* x       = (const float*)d_in[0];
    const float* patch_w = (const float*)d_in[1];
    const float* patch_b = (const float*)d_in[2];
    const float* cls     = (const float*)d_in[3];
    const float* pos     = (const float*)d_in[4];
    const float* Wq      = (const float*)d_in[5];
    const float* Wk      = (const float*)d_in[6];
    const float* Wv      = (const float*)d_in[7];
    const float* Wg      = (const float*)d_in[8];
    const float* Wo      = (const float*)d_in[9];
    const float* ln1_s   = (const float*)d_in[10];
    const float* ln1_b   = (const float*)d_in[11];
    const float* w1      = (const float*)d_in[12];
    const float* b1      = (const float*)d_in[13];
    const float* w2      = (const float*)d_in[14];
    const float* b2      = (const float*)d_in[15];
    const float* ln2_s   = (const float*)d_in[16];
    const float* ln2_b   = (const float*)d_in[17];
    const float* lnf_s   = (const float*)d_in[18];
    const float* lnf_b   = (const float*)d_in[19];
    const float* neck_w  = (const float*)d_in[20];
    const float* neck_b  = (const float*)d_in[21];
    const float* head_w  = (const float*)d_in[22];
    const float* head_b  = (const float*)d_in[23];
    float* out = (float*)d_out;

    int nimg = in_sizes[0] / 3072;
    cudaFuncSetAttribute(vit_kernel, cudaFuncAttributeMaxDynamicSharedMemorySize,
                         SMEMF * (int)sizeof(float));
    int blocks = (nimg + WPB - 1) / WPB;
    if (blocks < 1) blocks = 1;
    vit_kernel<<<blocks, 256, SMEMF * sizeof(float)>>>(
        x, patch_w, patch_b, cls, pos, Wq, Wk, Wv, Wg, Wo,
        ln1_s, ln1_b, w1, b1, w2, b2, ln2_s, ln2_b, lnf_s, lnf_b,
        neck_w, neck_b, head_w, head_b, out, nimg);
}

// round 11
// speedup vs baseline: 1.1461x; 1.1461x over previous
#include <cuda_runtime.h>
#include <math.h>

#define IPB 8                       // images per CTA (one warp-pair each)
#define PWI 6800                    // floats per image: Xs 1156 + Qs 1156 + Ks 1156 + Vs 2176 + Ssc 1156
#define TABF 1904                   // dmask 4*17*20 + sin 272 + cos 272
#define SMEMF (IPB*PWI + TABF)

__device__ __forceinline__ float wsum(float v) {
#pragma unroll
    for (int d = 16; d > 0; d >>= 1) v += __shfl_xor_sync(0xffffffffu, v, d);
    return v;
}

__global__ void __launch_bounds__(512, 1) vit_kernel(
    const float* __restrict__ x,      const float* __restrict__ patch_w,
    const float* __restrict__ patch_b,const float* __restrict__ cls,
    const float* __restrict__ pos,
    const float* __restrict__ Wq, const float* __restrict__ Wk,
    const float* __restrict__ Wv, const float* __restrict__ Wg,
    const float* __restrict__ Wo,
    const float* __restrict__ ln1_s, const float* __restrict__ ln1_b,
    const float* __restrict__ w1, const float* __restrict__ b1,
    const float* __restrict__ w2, const float* __restrict__ b2,
    const float* __restrict__ ln2_s, const float* __restrict__ ln2_b,
    const float* __restrict__ lnf_s, const float* __restrict__ lnf_b,
    const float* __restrict__ neck_w, const float* __restrict__ neck_b,
    const float* __restrict__ head_w, const float* __restrict__ head_b,
    float* __restrict__ out, int nimg)
{
    extern __shared__ float sm[];
    const int tid  = threadIdx.x;
    const int warp = tid >> 5, lane = tid & 31;
    const int pair = warp >> 1;          // image slot within CTA (0..7)
    const int wsel = warp & 1;           // 0: even tokens (incl cls), 1: odd tokens
    const int plane = (wsel << 5) | lane;// 0..63 within pair
    const int barid = pair + 1;          // named barrier per pair

#define PBAR() asm volatile("bar.sync %0, 64;" :: "r"(barid) : "memory")

    float* wb = sm + pair * PWI;
    float* Xs = wb;                 // [17][68]   (patch staging [192][16] overlaps Xs/Qs/Ks)
    float* Qs = wb + 1156;          // [17][68]   (reused: Gf[204], neck scratch)
    float* Ks = wb + 2312;          // [17][68]
    float* Vs = wb + 3468;          // [17][128]  (reused: Gs[17][128])
    float* Ssc= wb + 5644;          // [68][17]   normalized scores (dmask+den folded)
    float* tab = sm + IPB * PWI;
    float* DM = tab;                // [4][17][20]
    float* SN = tab + 1360;         // [17][16]
    float* CS = tab + 1632;         // [17][16]

    // ---- per-CTA tables ----
    if (tid < 68) {
        int hh = tid / 17, n = tid % 17;
        float l0 = logf(1.0f / 32.0f), l1 = logf(1.0f / 512.0f);
        float gam = 1.0f - expf(l0 + (l1 - l0) * ((float)hh / 3.0f));
        float lg = logf(gam);
        float row[17]; float s = 0.f;
#pragma unroll
        for (int m = 0; m < 17; m++) {
            float v = (m <= n) ? expf(lg * (float)(n - m)) : 0.f;
            row[m] = v; s += v;
        }
        float nf = rsqrtf(s) * 0.25f;    // QH^-0.5 folded in
#pragma unroll
        for (int m = 0; m < 17; m++) DM[(hh * 17 + n) * 20 + m] = row[m] * nf;
    }
    if (tid < 272) {
        int t = tid >> 4, j = tid & 15;
        float e = (float)(j >> 1) / 7.0f;
        float ang = expf(-e * logf(10000.0f));
        float a = (float)t * ang;
        SN[tid] = sinf(a); CS[tid] = cosf(a);
    }
    __syncthreads();

    const int col = lane * 2;    // lane's 2 cols of D=64 tensors
    const int c4  = lane * 4;    // lane's 4 cols of V=128 tensors
    const int hh4 = lane >> 3;   // head owning cols c4..c4+3

    // this warp's tokens: t = 2j + wsel (j = 0..8, valid while t < 17)
    for (int img = blockIdx.x * IPB + pair; img < nimg; img += gridDim.x * IPB) {
        // ================= patch embed =================
        const float* xi = x + (long)img * 3072;
        for (int i = plane; i < 3072; i += 64) {
            int c = i >> 10, rem = i & 1023, yy = rem >> 5, xx = rem & 31;
            int p = ((yy >> 3) << 2) + (xx >> 3);
            int f = (c << 6) + ((yy & 7) << 3) + (xx & 7);
            wb[f * 16 + p] = xi[i];           // staging [192][16]
        }
        PBAR();
        float2 h2[9];
        {
            float2 acc[8];
#pragma unroll
            for (int p = 0; p < 8; p++) acc[p] = make_float2(0.f, 0.f);
            int pb0 = 1 - wsel;
#pragma unroll 1
            for (int f = 0; f < 192; f++) {
                float2 w = *(const float2*)(patch_w + f * 64 + col);
                const float* st = wb + f * 16 + pb0;
#pragma unroll
                for (int p = 0; p < 8; p++) {
                    float xv = st[2 * p];
                    acc[p].x += xv * w.x; acc[p].y += xv * w.y;
                }
            }
            float2 pb = *(const float2*)(patch_b + col);
            if (wsel == 0) {
                float2 cl = *(const float2*)(cls + col);
                float2 p0 = *(const float2*)(pos + col);
                h2[0] = make_float2(cl.x + p0.x, cl.y + p0.y);
#pragma unroll
                for (int jj = 0; jj < 8; jj++) {          // tokens 2,4,..,16
                    int t = 2 + 2 * jj;
                    float2 po = *(const float2*)(pos + t * 64 + col);
                    h2[1 + jj] = make_float2(acc[jj].x + pb.x + po.x,
                                             acc[jj].y + pb.y + po.y);
                }
            } else {
#pragma unroll
                for (int jj = 0; jj < 8; jj++) {          // tokens 1,3,..,15
                    int t = 1 + 2 * jj;
                    float2 po = *(const float2*)(pos + t * 64 + col);
                    h2[jj] = make_float2(acc[jj].x + pb.x + po.x,
                                         acc[jj].y + pb.y + po.y);
                }
            }
        }
        PBAR();   // staging reads done before LN1 overwrites Xs

        // ================= transformer layers =================
#pragma unroll 1
        for (int L = 0; L < 8; L++) {
            const float* wq = Wq + L * 4096;
            const float* wk = Wk + L * 4096;
            const float* wv = Wv + L * 8192;
            const float* wg = Wg + L * 8192;
            const float* wo = Wo + L * 8192;

            // ---- LN1 -> Xs (own tokens) ----
            {
                float2 ls = *(const float2*)(ln1_s + L * 64 + col);
                float2 lb = *(const float2*)(ln1_b + L * 64 + col);
#pragma unroll
                for (int j = 0; j < 9; j++) {
                    int t = 2 * j + wsel;
                    if (t < 17) {
                        float s = wsum(h2[j].x + h2[j].y);
                        float q = wsum(h2[j].x * h2[j].x + h2[j].y * h2[j].y);
                        float mu = s * (1.0f / 64.0f);
                        float var = q * (1.0f / 64.0f) - mu * mu;
                        float r = rsqrtf(var + 1e-5f);
                        *(float2*)(Xs + t * 68 + col) =
                            make_float2((h2[j].x - mu) * r * ls.x + lb.x,
                                        (h2[j].y - mu) * r * ls.y + lb.y);
                    }
                }
            }
            __syncwarp();

            // ---- q,k = Xs @ Wq/Wk (own tokens), rope -> Qs,Ks ----
            {
                float2 qa[9], ka[9];
#pragma unroll
                for (int j = 0; j < 9; j++) { qa[j] = make_float2(0,0); ka[j] = make_float2(0,0); }
#pragma unroll 1
                for (int k0 = 0; k0 < 64; k0 += 4) {
                    float2 a0 = *(const float2*)(wq + (k0+0)*64 + col);
                    float2 a1 = *(const float2*)(wq + (k0+1)*64 + col);
                    float2 a2 = *(const float2*)(wq + (k0+2)*64 + col);
                    float2 a3 = *(const float2*)(wq + (k0+3)*64 + col);
                    float2 b0 = *(const float2*)(wk + (k0+0)*64 + col);
                    float2 b1 = *(const float2*)(wk + (k0+1)*64 + col);
                    float2 b2v= *(const float2*)(wk + (k0+2)*64 + col);
                    float2 b3 = *(const float2*)(wk + (k0+3)*64 + col);
#pragma unroll
                    for (int j = 0; j < 9; j++) {
                        int t = 2 * j + wsel;
                        if (t < 17) {
                            float4 xv = *(const float4*)(Xs + t * 68 + k0);
                            qa[j].x += xv.x*a0.x + xv.y*a1.x + xv.z*a2.x + xv.w*a3.x;
                            qa[j].y += xv.x*a0.y + xv.y*a1.y + xv.z*a2.y + xv.w*a3.y;
                            ka[j].x += xv.x*b0.x + xv.y*b1.x + xv.z*b2v.x + xv.w*b3.x;
                            ka[j].y += xv.x*b0.y + xv.y*b1.y + xv.z*b2v.y + xv.w*b3.y;
                        }
                    }
                }
                int cc = col & 15;
#pragma unroll
                for (int j = 0; j < 9; j++) {
                    int t = 2 * j + wsel;
                    if (t < 17) {
                        float sn = SN[t * 16 + cc], cn = CS[t * 16 + cc];
                        *(float2*)(Qs + t*68 + col) =
                            make_float2(qa[j].x*cn - qa[j].y*sn, qa[j].y*cn + qa[j].x*sn);
                        *(float2*)(Ks + t*68 + col) =
                            make_float2(ka[j].x*cn - ka[j].y*sn, ka[j].y*cn + ka[j].x*sn);
                    }
                }
            }

            // ---- v = Xs @ Wv (own tokens) -> Vs ----
            {
                float4 va[9];
#pragma unroll
                for (int j = 0; j < 9; j++) va[j] = make_float4(0,0,0,0);
#pragma unroll 1
                for (int k0 = 0; k0 < 64; k0 += 2) {
                    float4 v0 = *(const float4*)(wv + (k0+0)*128 + c4);
                    float4 v1 = *(const float4*)(wv + (k0+1)*128 + c4);
#pragma unroll
                    for (int j = 0; j < 9; j++) {
                        int t = 2 * j + wsel;
                        if (t < 17) {
                            float2 xv = *(const float2*)(Xs + t * 68 + k0);
                            va[j].x += xv.x*v0.x + xv.y*v1.x;
                            va[j].y += xv.x*v0.y + xv.y*v1.y;
                            va[j].z += xv.x*v0.z + xv.y*v1.z;
                            va[j].w += xv.x*v0.w + xv.y*v1.w;
                        }
                    }
                }
#pragma unroll
                for (int j = 0; j < 9; j++) {
                    int t = 2 * j + wsel;
                    if (t < 17) *(float4*)(Vs + t * 128 + c4) = va[j];
                }
            }
            PBAR();   // Qs, Ks, Vs complete

            // ---- stage A: normalized scores -> Ssc[68][17] ----
#pragma unroll 1
            for (int r = plane; r < 68; r += 64) {
                int hh = r & 3, n = r >> 2;
                const float* qp = Qs + n * 68 + hh * 16;
                float4 q0 = *(const float4*)(qp);
                float4 q1 = *(const float4*)(qp + 4);
                float4 q2 = *(const float4*)(qp + 8);
                float4 q3 = *(const float4*)(qp + 12);
                const float* dmr = DM + (hh * 17 + n) * 20;
                float sv[17]; float ssum = 0.f;
#pragma unroll
                for (int m = 0; m < 17; m++) {
                    if (m <= n) {
                        const float* kp = Ks + m * 68 + hh * 16;
                        float4 k0 = *(const float4*)(kp);
                        float4 k1 = *(const float4*)(kp + 4);
                        float4 k2 = *(const float4*)(kp + 8);
                        float4 k3 = *(const float4*)(kp + 12);
                        float s = q0.x*k0.x + q0.y*k0.y + q0.z*k0.z + q0.w*k0.w
                                + q1.x*k1.x + q1.y*k1.y + q1.z*k1.z + q1.w*k1.w
                                + q2.x*k2.x + q2.y*k2.y + q2.z*k2.z + q2.w*k2.w
                                + q3.x*k3.x + q3.y*k3.y + q3.z*k3.z + q3.w*k3.w;
                        s *= dmr[m];
                        sv[m] = s; ssum += s;
                    }
                }
                float den = fabsf(ssum); den = den > 1.f ? den : 1.f;
                float inv = 1.f / den;
                float* sp = Ssc + (hh * 17 + n) * 17;
#pragma unroll
                for (int m = 0; m < 17; m++) if (m <= n) sp[m] = sv[m] * inv;
            }
            PBAR();   // Ssc complete

            // ---- stage B: o = S @ v (own tokens) + per-head groupnorm ----
            float4 ov[9];
            {
#pragma unroll
                for (int j = 0; j < 9; j++) ov[j] = make_float4(0,0,0,0);
#pragma unroll
                for (int j = 0; j < 9; j++) {
                    int n = 2 * j + wsel;
                    if (n < 17) {
                        const float* sp = Ssc + (hh4 * 17 + n) * 17;
                        float4 o = make_float4(0,0,0,0);
#pragma unroll 1
                        for (int m = 0; m <= n; m++) {
                            float sc = sp[m];
                            float4 vm = *(const float4*)(Vs + m * 128 + c4);
                            o.x += sc * vm.x; o.y += sc * vm.y;
                            o.z += sc * vm.z; o.w += sc * vm.w;
                        }
                        float pm = o.x + o.y + o.z + o.w;
                        float pq = o.x*o.x + o.y*o.y + o.z*o.z + o.w*o.w;
#pragma unroll
                        for (int d = 1; d < 8; d <<= 1) {
                            pm += __shfl_xor_sync(0xffffffffu, pm, d);
                            pq += __shfl_xor_sync(0xffffffffu, pq, d);
                        }
                        float mu = pm * (1.0f / 32.0f);
                        float var = pq * (1.0f / 32.0f) - mu * mu;
                        float rn = rsqrtf(var + 1e-5f);
                        ov[j] = make_float4((o.x - mu) * rn, (o.y - mu) * rn,
                                            (o.z - mu) * rn, (o.w - mu) * rn);
                    }
                }
            }

            // ---- g = Xs @ Wg (own tokens) ----
            float4 ga[9];
            {
#pragma unroll
                for (int j = 0; j < 9; j++) ga[j] = make_float4(0,0,0,0);
#pragma unroll 1
                for (int k0 = 0; k0 < 64; k0 += 2) {
                    float4 g0 = *(const float4*)(wg + (k0+0)*128 + c4);
                    float4 g1 = *(const float4*)(wg + (k0+1)*128 + c4);
#pragma unroll
                    for (int j = 0; j < 9; j++) {
                        int t = 2 * j + wsel;
                        if (t < 17) {
                            float2 xv = *(const float2*)(Xs + t * 68 + k0);
                            ga[j].x += xv.x*g0.x + xv.y*g1.x;
                            ga[j].y += xv.x*g0.y + xv.y*g1.y;
                            ga[j].z += xv.x*g0.z + xv.y*g1.z;
                            ga[j].w += xv.x*g0.w + xv.y*g1.w;
                        }
                    }
                }
            }
            PBAR();   // all Vs reads done; Gs may overwrite Vs

            // ---- Gs = silu(g) * ov  (overlays Vs) ----
            {
                float* Gs = Vs;
#pragma unroll
                for (int j = 0; j < 9; j++) {
                    int t = 2 * j + wsel;
                    if (t < 17) {
                        float4 g = ga[j];
                        float4 o = ov[j];
                        float4 rr;
                        rr.x = g.x / (1.f + expf(-g.x)) * o.x;
                        rr.y = g.y / (1.f + expf(-g.y)) * o.y;
                        rr.z = g.z / (1.f + expf(-g.z)) * o.z;
                        rr.w = g.w / (1.f + expf(-g.w)) * o.w;
                        *(float4*)(Gs + t * 128 + c4) = rr;
                    }
                }
            }
            PBAR();   // Gs complete

            // ---- attn out = Gs @ Wo (own tokens), residual ----
            {
                const float* Gs = Vs;
                float2 ao[9];
#pragma unroll
                for (int j = 0; j < 9; j++) ao[j] = make_float2(0,0);
#pragma unroll 1
                for (int k0 = 0; k0 < 128; k0 += 4) {
                    float2 w0 = *(const float2*)(wo + (k0+0)*64 + col);
                    float2 w1 = *(const float2*)(wo + (k0+1)*64 + col);
                    float2 w2 = *(const float2*)(wo + (k0+2)*64 + col);
                    float2 w3 = *(const float2*)(wo + (k0+3)*64 + col);
#pragma unroll
                    for (int j = 0; j < 9; j++) {
                        int t = 2 * j + wsel;
                        if (t < 17) {
                            float4 gv = *(const float4*)(Gs + t * 128 + k0);
                            ao[j].x += gv.x*w0.x + gv.y*w1.x + gv.z*w2.x + gv.w*w3.x;
                            ao[j].y += gv.x*w0.y + gv.y*w1.y + gv.z*w2.y + gv.w*w3.y;
                        }
                    }
                }
#pragma unroll
                for (int j = 0; j < 9; j++) { h2[j].x += ao[j].x; h2[j].y += ao[j].y; }
            }

            // ---- LN2 -> Xs (own tokens) ----
            {
                float2 ls = *(const float2*)(ln2_s + L * 64 + col);
                float2 lb = *(const float2*)(ln2_b + L * 64 + col);
#pragma unroll
                for (int j = 0; j < 9; j++) {
                    int t = 2 * j + wsel;
                    if (t < 17) {
                        float s = wsum(h2[j].x + h2[j].y);
                        float q = wsum(h2[j].x * h2[j].x + h2[j].y * h2[j].y);
                        float mu = s * (1.0f / 64.0f);
                        float var = q * (1.0f / 64.0f) - mu * mu;
                        float r = rsqrtf(var + 1e-5f);
                        *(float2*)(Xs + t * 68 + col) =
                            make_float2((h2[j].x - mu) * r * ls.x + lb.x,
                                        (h2[j].y - mu) * r * ls.y + lb.y);
                    }
                }
            }
            PBAR();   // Xs complete (FFN1 reads all tokens)

            // ---- FFN: gelu(Xs @ w1 + b1) -> Gf (overlays Qs) ----
            {
                float* Gf = Qs;
                const float* pw1 = w1 + L * 768;
                const float* pb1 = b1 + L * 12;
#pragma unroll 1
                for (int r = plane; r < 204; r += 64) {
                    int t = r / 12, jj = r - t * 12;
                    float s = pb1[jj];
                    const float* xr = Xs + t * 68;
#pragma unroll
                    for (int k4 = 0; k4 < 64; k4 += 4) {
                        float4 xv = *(const float4*)(xr + k4);
                        s += xv.x * pw1[(k4+0)*12 + jj] + xv.y * pw1[(k4+1)*12 + jj]
                           + xv.z * pw1[(k4+2)*12 + jj] + xv.w * pw1[(k4+3)*12 + jj];
                    }
                    float c = 0.7978845608028654f * (s + 0.044715f * s * s * s);
                    Gf[r] = 0.5f * s * (1.f + tanhf(c));
                }
            }
            PBAR();   // Gf complete

            // ---- h += Gf @ w2 + b2 (own tokens) ----
            {
                const float* Gf = Qs;
                const float* pw2 = w2 + L * 768;
                float2 b2v = *(const float2*)(b2 + L * 64 + col);
                float2 wv2[12];
#pragma unroll
                for (int k = 0; k < 12; k++) wv2[k] = *(const float2*)(pw2 + k * 64 + col);
#pragma unroll
                for (int j = 0; j < 9; j++) {
                    int t = 2 * j + wsel;
                    if (t < 17) {
                        float ax = b2v.x, ay = b2v.y;
#pragma unroll
                        for (int k = 0; k < 12; k++) {
                            float gv = Gf[t * 12 + k];
                            ax += gv * wv2[k].x; ay += gv * wv2[k].y;
                        }
                        h2[j].x += ax; h2[j].y += ay;
                    }
                }
            }
            PBAR();   // Gf reads done before next layer overwrites Qs
        } // layers

        // ================= final LN (token 16, warp A) + neck + head =================
        if (wsel == 0) {
            float2 hv = h2[8];     // token 16
            float s = wsum(hv.x + hv.y);
            float q = wsum(hv.x * hv.x + hv.y * hv.y);
            float mu = s * (1.0f / 64.0f);
            float var = q * (1.0f / 64.0f) - mu * mu;
            float r = rsqrtf(var + 1e-5f);
            float2 ls = *(const float2*)(lnf_s + col);
            float2 lb = *(const float2*)(lnf_b + col);
            Xs[col]   = (hv.x - mu) * r * ls.x + lb.x;
            Xs[col+1] = (hv.y - mu) * r * ls.y + lb.y;
            __syncwarp();
            if (lane < 16) {
                float sv = neck_b[lane];
#pragma unroll
                for (int k = 0; k < 64; k++) sv += Xs[k] * neck_w[k * 16 + lane];
                Qs[lane] = sv;
            }
            __syncwarp();
            if (lane < 10) {
                float sv = head_b[lane];
#pragma unroll
                for (int k = 0; k < 16; k++) sv += Qs[k] * head_w[k * 10 + lane];
                out[(long)img * 10 + lane] = sv;
            }
        }
        PBAR();   // head done before next image's staging overwrites
    } // img loop
#undef PBAR
}

extern "C" void kernel_launch(void* const* d_in, const int* in_sizes, int n_in,
                              void* d_out, int out_size) {
    const float* x       = (const float*)d_in[0];
    const float* patch_w = (const float*)d_in[1];
    const float* patch_b = (const float*)d_in[2];
    const float* cls     = (const float*)d_in[3];
    const float* pos     = (const float*)d_in[4];
    const float* Wq      = (const float*)d_in[5];
    const float* Wk      = (const float*)d_in[6];
    const float* Wv      = (const float*)d_in[7];
    const float* Wg      = (const float*)d_in[8];
    const float* Wo      = (const float*)d_in[9];
    const float* ln1_s   = (const float*)d_in[10];
    const float* ln1_b   = (const float*)d_in[11];
    const float* w1      = (const float*)d_in[12];
    const float* b1      = (const float*)d_in[13];
    const float* w2      = (const float*)d_in[14];
    const float* b2      = (const float*)d_in[15];
    const float* ln2_s   = (const float*)d_in[16];
    const float* ln2_b   = (const float*)d_in[17];
    const float* lnf_s   = (const float*)d_in[18];
    const float* lnf_b   = (const float*)d_in[19];
    const float* neck_w  = (const float*)d_in[20];
    const float* neck_b  = (const float*)d_in[21];
    const float* head_w  = (const float*)d_in[22];
    const float* head_b  = (const float*)d_in[23];
    float* out = (float*)d_out;

    int nimg = in_sizes[0] / 3072;
    cudaFuncSetAttribute(vit_kernel, cudaFuncAttributeMaxDynamicSharedMemorySize,
                         SMEMF * (int)sizeof(float));
    int blocks = (nimg + IPB - 1) / IPB;
    if (blocks < 1) blocks = 1;
    vit_kernel<<<blocks, 512, SMEMF * sizeof(float)>>>(
        x, patch_w, patch_b, cls, pos, Wq, Wk, Wv, Wg, Wo,
        ln1_s, ln1_b, w1, b1, w2, b2, ln2_s, ln2_b, lnf_s, lnf_b,
        neck_w, neck_b, head_w, head_b, out, nimg);
}